// round 12
// baseline (speedup 1.0000x reference)
#include <cuda_runtime.h>
#include <cuda_fp16.h>

#define N_NODES 50000
#define N_EDGES 600000
#define IN_CH 128
#define HC 128
#define HEADS 4
#define NEG_SLOPE 0.2f
#define NPB 32
#define CAP 128        // per-node CSR capacity (mean deg 12)
#define NBLK_X 1563    // ceil(50000/32); 1563*384 >= 600000; >= 128 prep blocks
#define PREP_BLOCKS 128
#define NPAIRS (N_NODES / 2)
#define NODE_BLOCKS 1184            // ~exactly chip-resident at 256 thr
#define NODE_WARPS (NODE_BLOCKS * 8)

typedef unsigned long long ull;

// ---------------- scratch (device globals) -----------------------------------
__device__ float  g_Wt[IN_CH * HC];                  // [i][o]
__device__ float  g_bias[HC];
__device__ float  g_asrc[HC];
__device__ float  g_adst[HC];
__device__ __half g_xt_h[(size_t)N_NODES * HC];      // 12.8 MB fp16 features
__device__ float  g_alpha_src[N_NODES * HEADS];
__device__ float  g_alpha_dst[N_NODES * HEADS];
__device__ int    g_cnt[N_NODES];                    // degree counter; self-reset
__device__ int    g_csr_src[(size_t)N_NODES * CAP];  // 25.6 MB padded CSR
__device__ int    g_ready;                           // prep barrier; self-reset
__device__ int    g_work;                            // work-steal ticket; self-reset

// ---------------- f32x2 packed-math helpers -----------------------------------
__device__ __forceinline__ ull pk2(float a, float b) {
    ull r; asm("mov.b64 %0, {%1, %2};" : "=l"(r) : "f"(a), "f"(b)); return r;
}
__device__ __forceinline__ void upk2(ull v, float& a, float& b) {
    asm("mov.b64 {%0, %1}, %2;" : "=f"(a), "=f"(b) : "l"(v));
}
__device__ __forceinline__ ull fma2(ull a, ull b, ull c) {
    ull d; asm("fma.rn.f32x2 %0, %1, %2, %3;" : "=l"(d) : "l"(a), "l"(b), "l"(c)); return d;
}
__device__ __forceinline__ ull mul2(ull a, ull b) {
    ull d; asm("mul.rn.f32x2 %0, %1, %2;" : "=l"(d) : "l"(a), "l"(b)); return d;
}
__device__ __forceinline__ ull add2(ull a, ull b) {
    ull d; asm("add.rn.f32x2 %0, %1, %2;" : "=l"(d) : "l"(a), "l"(b)); return d;
}

// ---------------- kernel 1: fused scatter + prep + node transform --------------
__global__ void __launch_bounds__(128) k_fused(const float* __restrict__ x,
                                               const int* __restrict__ ei,
                                               const float* __restrict__ lw,
                                               const float* __restrict__ lb,
                                               const float* __restrict__ as,
                                               const float* __restrict__ ad,
                                               const float* __restrict__ ct) {
    int t = threadIdx.x;
    int bid = blockIdx.x;

    // (a) padded-CSR scatter, 3 edges per thread
    {
        int ebase = bid * 384;
        #pragma unroll
        for (int j = 0; j < 3; j++) {
            int e = ebase + j * 128 + t;
            if (e < N_EDGES) {
                int r = __ldg(&ei[e]);
                int c = __ldg(&ei[N_EDGES + e]);
                int pos = atomicAdd(&g_cnt[c], 1);
                if (pos < CAP) g_csr_src[c * CAP + pos] = r;
            }
        }
    }

    // (b) Bezier prep: block b handles output column o=b, thread t = input ch i
    if (bid < PREP_BLOCKS) {
        float c0 = __ldg(&ct[0]), c1 = __ldg(&ct[1]), c2 = __ldg(&ct[2]);
        float w = c0 * __ldg(&lw[bid * IN_CH + t])
                + c1 * __ldg(&lw[IN_CH * HC + bid * IN_CH + t])
                + c2 * __ldg(&lw[2 * IN_CH * HC + bid * IN_CH + t]);
        g_Wt[t * HC + bid] = w;
        if (bid == 0) {
            g_bias[t] = c0 * __ldg(&lb[t]) + c1 * __ldg(&lb[HC + t]) + c2 * __ldg(&lb[2 * HC + t]);
            g_asrc[t] = c0 * __ldg(&as[t]) + c1 * __ldg(&as[HC + t]) + c2 * __ldg(&as[2 * HC + t]);
            g_adst[t] = c0 * __ldg(&ad[t]) + c1 * __ldg(&ad[HC + t]) + c2 * __ldg(&ad[2 * HC + t]);
        }
        __syncthreads();
        if (t == 0) {
            __threadfence();
            atomicAdd(&g_ready, 1);
        }
    }

    // start the x-tile loads while waiting (independent of weights)
    __shared__ float2 xsp[16][IN_CH];
    int n0 = bid * NPB;
    #pragma unroll
    for (int p = 0; p < 16; p++) {
        int na = n0 + p, nb = n0 + p + 16;
        float2 f;
        f.x = (na < N_NODES) ? __ldg(&x[(size_t)na * IN_CH + t]) : 0.0f;
        f.y = (nb < N_NODES) ? __ldg(&x[(size_t)nb * IN_CH + t]) : 0.0f;
        xsp[p][t] = f;
    }

    // (c) device barrier: wait for all 128 prep blocks (they are wave-1 bids)
    if (t == 0) {
        int v;
        do {
            asm volatile("ld.acquire.gpu.global.b32 %0, [%1];" : "=r"(v) : "l"(&g_ready));
            if (v >= PREP_BLOCKS) break;
            __nanosleep(128);
        } while (true);
    }
    __syncthreads();   // also covers the xsp tile

    // (d) GEMM
    ull acc[16];
    float b = g_bias[t];
    ull b2 = pk2(b, b);
    #pragma unroll
    for (int p = 0; p < 16; p++) acc[p] = b2;

    #pragma unroll 2
    for (int i = 0; i < IN_CH; i += 2) {
        float w0 = g_Wt[i * HC + t];
        float w1 = g_Wt[(i + 1) * HC + t];
        ull w02 = pk2(w0, w0);
        ull w12 = pk2(w1, w1);
        #pragma unroll
        for (int p = 0; p < 16; p++) {
            longlong2 xv = *reinterpret_cast<const longlong2*>(&xsp[p][i]);
            acc[p] = fma2((ull)xv.x, w02, acc[p]);
            acc[p] = fma2((ull)xv.y, w12, acc[p]);
        }
    }

    int h = t >> 5;
    float a_s = g_asrc[t];
    float a_d = g_adst[t];
    ull as2 = pk2(a_s, a_s);
    ull ad2 = pk2(a_d, a_d);

    #pragma unroll
    for (int p = 0; p < 16; p++) {
        int na = n0 + p, nb = n0 + p + 16;
        float lo, hi;
        upk2(acc[p], lo, hi);
        if (na < N_NODES) g_xt_h[(size_t)na * HC + t] = __float2half_rn(lo);
        if (nb < N_NODES) g_xt_h[(size_t)nb * HC + t] = __float2half_rn(hi);

        ull vs = mul2(acc[p], as2);
        ull vd = mul2(acc[p], ad2);
        #pragma unroll
        for (int off = 16; off > 0; off >>= 1) {
            vs = add2(vs, __shfl_xor_sync(0xffffffffu, vs, off));
            vd = add2(vd, __shfl_xor_sync(0xffffffffu, vd, off));
        }
        if ((t & 31) == 0) {
            float vsl, vsh, vdl, vdh;
            upk2(vs, vsl, vsh);
            upk2(vd, vdl, vdh);
            if (na < N_NODES) {
                g_alpha_src[na * HEADS + h] = vsl;
                g_alpha_dst[na * HEADS + h] = vdl;
            }
            if (nb < N_NODES) {
                g_alpha_src[nb * HEADS + h] = vsh;
                g_alpha_dst[nb * HEADS + h] = vdh;
            }
        }
    }
}

// ---------------- kernel 2: persistent softmax+agg with warp work-stealing -----
// 2 nodes per warp (16 lanes/node, 8 ch/lane). Warps pull node-pair tickets
// from g_work; no wave quantization, no block-level tail. Counter self-resets
// via the last failing ticket (all atomics complete by then).
__global__ void __launch_bounds__(256) k_node(float* __restrict__ out) {
    int lane = threadIdx.x & 31;
    int l = lane & 15;
    int h = l >> 2;
    const uint4* xt4 = (const uint4*)g_xt_h;

    while (true) {
        int pair;
        if (lane == 0) pair = atomicAdd(&g_work, 1);
        pair = __shfl_sync(0xffffffffu, pair, 0);
        if (pair >= NPAIRS) {
            // exactly NODE_WARPS failing tickets; holder of the last one resets
            if (lane == 0 && pair == NPAIRS + NODE_WARPS - 1) {
                atomicExch(&g_work, 0);
                g_ready = 0;
            }
            return;
        }

        int node = pair * 2 + (lane >> 4);
        int deg = g_cnt[node];
        if (deg > CAP) deg = CAP;
        unsigned base = (unsigned)node * CAP;
        float ad = __ldg(&g_alpha_dst[node * HEADS + h]);

        float denom = 0.0f;
        float acc[8];
        #pragma unroll
        for (int k = 0; k < 8; k++) acc[k] = 0.0f;

        int e = 0;
        for (; e + 4 <= deg; e += 4) {
            int s[4]; float a[4]; uint4 u[4];
            #pragma unroll
            for (int j = 0; j < 4; j++) s[j] = __ldg(&g_csr_src[base + e + j]);
            #pragma unroll
            for (int j = 0; j < 4; j++) a[j] = __ldg(&g_alpha_src[s[j] * HEADS + h]) + ad;
            #pragma unroll
            for (int j = 0; j < 4; j++) u[j] = __ldg(&xt4[(unsigned)s[j] * 16 + l]);
            #pragma unroll
            for (int j = 0; j < 4; j++) {
                float aj = a[j];
                aj = (aj > 0.f) ? aj : NEG_SLOPE * aj;
                float ex = __expf(aj);
                denom += ex;
                float2 p0 = __half22float2(*(const __half2*)&u[j].x);
                float2 p1 = __half22float2(*(const __half2*)&u[j].y);
                float2 p2 = __half22float2(*(const __half2*)&u[j].z);
                float2 p3 = __half22float2(*(const __half2*)&u[j].w);
                acc[0] = fmaf(p0.x, ex, acc[0]);
                acc[1] = fmaf(p0.y, ex, acc[1]);
                acc[2] = fmaf(p1.x, ex, acc[2]);
                acc[3] = fmaf(p1.y, ex, acc[3]);
                acc[4] = fmaf(p2.x, ex, acc[4]);
                acc[5] = fmaf(p2.y, ex, acc[5]);
                acc[6] = fmaf(p3.x, ex, acc[6]);
                acc[7] = fmaf(p3.y, ex, acc[7]);
            }
        }
        for (; e < deg; e++) {
            int s = __ldg(&g_csr_src[base + e]);
            float a = __ldg(&g_alpha_src[s * HEADS + h]) + ad;
            a = (a > 0.f) ? a : NEG_SLOPE * a;
            uint4 u = __ldg(&xt4[(unsigned)s * 16 + l]);
            float ex = __expf(a);
            denom += ex;
            float2 p0 = __half22float2(*(const __half2*)&u.x);
            float2 p1 = __half22float2(*(const __half2*)&u.y);
            float2 p2 = __half22float2(*(const __half2*)&u.z);
            float2 p3 = __half22float2(*(const __half2*)&u.w);
            acc[0] = fmaf(p0.x, ex, acc[0]);
            acc[1] = fmaf(p0.y, ex, acc[1]);
            acc[2] = fmaf(p1.x, ex, acc[2]);
            acc[3] = fmaf(p1.y, ex, acc[3]);
            acc[4] = fmaf(p2.x, ex, acc[4]);
            acc[5] = fmaf(p2.y, ex, acc[5]);
            acc[6] = fmaf(p3.x, ex, acc[6]);
            acc[7] = fmaf(p3.y, ex, acc[7]);
        }

        float inv = 1.0f / (denom + 1e-16f);
        float4* o4 = (float4*)out;
        unsigned obase = (unsigned)node * 32 + l * 2;
        o4[obase]     = make_float4(acc[0] * inv, acc[1] * inv, acc[2] * inv, acc[3] * inv);
        o4[obase + 1] = make_float4(acc[4] * inv, acc[5] * inv, acc[6] * inv, acc[7] * inv);

        if (l == 0) g_cnt[node] = 0;   // self-reset for next graph replay
    }
}

// ---------------------------------------------------------------------------
extern "C" void kernel_launch(void* const* d_in, const int* in_sizes, int n_in,
                              void* d_out, int out_size) {
    const float* x  = (const float*)d_in[0];
    const int*   ei = (const int*)d_in[1];
    const float* ct = (const float*)d_in[2];
    const float* lw = (const float*)d_in[3];
    const float* lb = (const float*)d_in[4];
    const float* as = (const float*)d_in[5];
    const float* ad = (const float*)d_in[6];
    float* out = (float*)d_out;

    k_fused<<<NBLK_X, 128>>>(x, ei, lw, lb, as, ad, ct);
    k_node<<<NODE_BLOCKS, 256>>>(out);
}

// round 13
// speedup vs baseline: 1.0691x; 1.0691x over previous
#include <cuda_runtime.h>
#include <cuda_fp16.h>

#define N_NODES 50000
#define N_EDGES 600000
#define IN_CH 128
#define HC 128
#define HEADS 4
#define NEG_SLOPE 0.2f
#define NPB 32
#define CAP 128        // per-node CSR capacity (mean deg 12)
#define NBLK_X 1563    // ceil(50000/32); 1563*384 >= 600000; >= 128 prep blocks
#define PREP_BLOCKS 128

typedef unsigned long long ull;

// ---------------- scratch (device globals) -----------------------------------
__device__ float  g_Wt[IN_CH * HC];                  // [i][o]
__device__ float  g_bias[HC];
__device__ float  g_asrc[HC];
__device__ float  g_adst[HC];
__device__ __half g_xt_h[(size_t)N_NODES * HC];      // 12.8 MB fp16 features
__device__ float  g_alpha_src[N_NODES * HEADS];
__device__ float  g_alpha_dst[N_NODES * HEADS];
__device__ int    g_cnt[N_NODES];                    // degree counter; self-reset
__device__ int    g_csr_src[(size_t)N_NODES * CAP];  // 25.6 MB padded CSR
__device__ int    g_ready;                           // prep barrier; self-reset

// ---------------- f32x2 packed-math helpers -----------------------------------
__device__ __forceinline__ ull pk2(float a, float b) {
    ull r; asm("mov.b64 %0, {%1, %2};" : "=l"(r) : "f"(a), "f"(b)); return r;
}
__device__ __forceinline__ void upk2(ull v, float& a, float& b) {
    asm("mov.b64 {%0, %1}, %2;" : "=f"(a), "=f"(b) : "l"(v));
}
__device__ __forceinline__ ull fma2(ull a, ull b, ull c) {
    ull d; asm("fma.rn.f32x2 %0, %1, %2, %3;" : "=l"(d) : "l"(a), "l"(b), "l"(c)); return d;
}
__device__ __forceinline__ ull mul2(ull a, ull b) {
    ull d; asm("mul.rn.f32x2 %0, %1, %2;" : "=l"(d) : "l"(a), "l"(b)); return d;
}
__device__ __forceinline__ ull add2(ull a, ull b) {
    ull d; asm("add.rn.f32x2 %0, %1, %2;" : "=l"(d) : "l"(a), "l"(b)); return d;
}

// ---------------- kernel 1: fused scatter + prep + node transform --------------
__global__ void __launch_bounds__(128) k_fused(const float* __restrict__ x,
                                               const int* __restrict__ ei,
                                               const float* __restrict__ lw,
                                               const float* __restrict__ lb,
                                               const float* __restrict__ as,
                                               const float* __restrict__ ad,
                                               const float* __restrict__ ct) {
    int t = threadIdx.x;
    int bid = blockIdx.x;

    // (a) padded-CSR scatter, 3 edges per thread (hidden under the GEMM)
    {
        int ebase = bid * 384;
        #pragma unroll
        for (int j = 0; j < 3; j++) {
            int e = ebase + j * 128 + t;
            if (e < N_EDGES) {
                int r = __ldg(&ei[e]);
                int c = __ldg(&ei[N_EDGES + e]);
                int pos = atomicAdd(&g_cnt[c], 1);
                if (pos < CAP) g_csr_src[c * CAP + pos] = r;
            }
        }
    }

    // (b) Bezier prep: block b handles output column o=b, thread t = input ch i
    if (bid < PREP_BLOCKS) {
        float c0 = __ldg(&ct[0]), c1 = __ldg(&ct[1]), c2 = __ldg(&ct[2]);
        float w = c0 * __ldg(&lw[bid * IN_CH + t])
                + c1 * __ldg(&lw[IN_CH * HC + bid * IN_CH + t])
                + c2 * __ldg(&lw[2 * IN_CH * HC + bid * IN_CH + t]);
        g_Wt[t * HC + bid] = w;
        if (bid == 0) {
            g_bias[t] = c0 * __ldg(&lb[t]) + c1 * __ldg(&lb[HC + t]) + c2 * __ldg(&lb[2 * HC + t]);
            g_asrc[t] = c0 * __ldg(&as[t]) + c1 * __ldg(&as[HC + t]) + c2 * __ldg(&as[2 * HC + t]);
            g_adst[t] = c0 * __ldg(&ad[t]) + c1 * __ldg(&ad[HC + t]) + c2 * __ldg(&ad[2 * HC + t]);
        }
        __syncthreads();
        if (t == 0) {
            __threadfence();
            atomicAdd(&g_ready, 1);
        }
    }

    // start the x-tile loads while waiting (independent of weights)
    __shared__ float2 xsp[16][IN_CH];
    int n0 = bid * NPB;
    #pragma unroll
    for (int p = 0; p < 16; p++) {
        int na = n0 + p, nb = n0 + p + 16;
        float2 f;
        f.x = (na < N_NODES) ? __ldg(&x[(size_t)na * IN_CH + t]) : 0.0f;
        f.y = (nb < N_NODES) ? __ldg(&x[(size_t)nb * IN_CH + t]) : 0.0f;
        xsp[p][t] = f;
    }

    // (c) device barrier: wait for all 128 prep blocks (they are wave-1 bids)
    if (t == 0) {
        int v;
        do {
            asm volatile("ld.acquire.gpu.global.b32 %0, [%1];" : "=r"(v) : "l"(&g_ready));
            if (v >= PREP_BLOCKS) break;
            __nanosleep(128);
        } while (true);
    }
    __syncthreads();   // also covers the xsp tile

    // (d) GEMM
    ull acc[16];
    float b = g_bias[t];
    ull b2 = pk2(b, b);
    #pragma unroll
    for (int p = 0; p < 16; p++) acc[p] = b2;

    #pragma unroll 2
    for (int i = 0; i < IN_CH; i += 2) {
        float w0 = g_Wt[i * HC + t];
        float w1 = g_Wt[(i + 1) * HC + t];
        ull w02 = pk2(w0, w0);
        ull w12 = pk2(w1, w1);
        #pragma unroll
        for (int p = 0; p < 16; p++) {
            longlong2 xv = *reinterpret_cast<const longlong2*>(&xsp[p][i]);
            acc[p] = fma2((ull)xv.x, w02, acc[p]);
            acc[p] = fma2((ull)xv.y, w12, acc[p]);
        }
    }

    int h = t >> 5;
    float a_s = g_asrc[t];
    float a_d = g_adst[t];
    ull as2 = pk2(a_s, a_s);
    ull ad2 = pk2(a_d, a_d);

    #pragma unroll
    for (int p = 0; p < 16; p++) {
        int na = n0 + p, nb = n0 + p + 16;
        float lo, hi;
        upk2(acc[p], lo, hi);
        if (na < N_NODES) g_xt_h[(size_t)na * HC + t] = __float2half_rn(lo);
        if (nb < N_NODES) g_xt_h[(size_t)nb * HC + t] = __float2half_rn(hi);

        ull vs = mul2(acc[p], as2);
        ull vd = mul2(acc[p], ad2);
        #pragma unroll
        for (int off = 16; off > 0; off >>= 1) {
            vs = add2(vs, __shfl_xor_sync(0xffffffffu, vs, off));
            vd = add2(vd, __shfl_xor_sync(0xffffffffu, vd, off));
        }
        if ((t & 31) == 0) {
            float vsl, vsh, vdl, vdh;
            upk2(vs, vsl, vsh);
            upk2(vd, vdl, vdh);
            if (na < N_NODES) {
                g_alpha_src[na * HEADS + h] = vsl;
                g_alpha_dst[na * HEADS + h] = vdl;
            }
            if (nb < N_NODES) {
                g_alpha_src[nb * HEADS + h] = vsh;
                g_alpha_dst[nb * HEADS + h] = vdh;
            }
        }
    }
}

// ---------------- kernel 2: fused softmax (no-max) + aggregation ---------------
// Static 2 nodes/warp; chunk-2 gather loop (4 independent 256B gathers in
// flight per warp); reg-capped for 8 blocks/SM occupancy.
__global__ void __launch_bounds__(256, 8) k_node(float* __restrict__ out) {
    int pair = (int)(((long long)blockIdx.x * blockDim.x + threadIdx.x) >> 5);
    if (pair >= N_NODES / 2) return;
    int lane = threadIdx.x & 31;
    int node = pair * 2 + (lane >> 4);
    int l = lane & 15;
    int h = l >> 2;

    int deg = g_cnt[node];
    if (deg > CAP) deg = CAP;
    unsigned base = (unsigned)node * CAP;
    float ad = __ldg(&g_alpha_dst[node * HEADS + h]);

    float denom = 0.0f;
    float acc[8];
    #pragma unroll
    for (int k = 0; k < 8; k++) acc[k] = 0.0f;

    const uint4* xt4 = (const uint4*)g_xt_h;

    int e = 0;
    for (; e + 2 <= deg; e += 2) {
        int s0 = __ldg(&g_csr_src[base + e]);
        int s1 = __ldg(&g_csr_src[base + e + 1]);
        float a0 = __ldg(&g_alpha_src[s0 * HEADS + h]) + ad;
        float a1 = __ldg(&g_alpha_src[s1 * HEADS + h]) + ad;
        uint4 u0 = __ldg(&xt4[(unsigned)s0 * 16 + l]);
        uint4 u1 = __ldg(&xt4[(unsigned)s1 * 16 + l]);
        a0 = (a0 > 0.f) ? a0 : NEG_SLOPE * a0;
        a1 = (a1 > 0.f) ? a1 : NEG_SLOPE * a1;
        float e0 = __expf(a0);
        float e1 = __expf(a1);
        denom += e0 + e1;

        float2 q0 = __half22float2(*(const __half2*)&u0.x);
        float2 q1 = __half22float2(*(const __half2*)&u0.y);
        float2 q2 = __half22float2(*(const __half2*)&u0.z);
        float2 q3 = __half22float2(*(const __half2*)&u0.w);
        acc[0] = fmaf(q0.x, e0, acc[0]);
        acc[1] = fmaf(q0.y, e0, acc[1]);
        acc[2] = fmaf(q1.x, e0, acc[2]);
        acc[3] = fmaf(q1.y, e0, acc[3]);
        acc[4] = fmaf(q2.x, e0, acc[4]);
        acc[5] = fmaf(q2.y, e0, acc[5]);
        acc[6] = fmaf(q3.x, e0, acc[6]);
        acc[7] = fmaf(q3.y, e0, acc[7]);
        q0 = __half22float2(*(const __half2*)&u1.x);
        q1 = __half22float2(*(const __half2*)&u1.y);
        q2 = __half22float2(*(const __half2*)&u1.z);
        q3 = __half22float2(*(const __half2*)&u1.w);
        acc[0] = fmaf(q0.x, e1, acc[0]);
        acc[1] = fmaf(q0.y, e1, acc[1]);
        acc[2] = fmaf(q1.x, e1, acc[2]);
        acc[3] = fmaf(q1.y, e1, acc[3]);
        acc[4] = fmaf(q2.x, e1, acc[4]);
        acc[5] = fmaf(q2.y, e1, acc[5]);
        acc[6] = fmaf(q3.x, e1, acc[6]);
        acc[7] = fmaf(q3.y, e1, acc[7]);
    }
    if (e < deg) {
        int s = __ldg(&g_csr_src[base + e]);
        float a = __ldg(&g_alpha_src[s * HEADS + h]) + ad;
        a = (a > 0.f) ? a : NEG_SLOPE * a;
        uint4 u = __ldg(&xt4[(unsigned)s * 16 + l]);
        float ex = __expf(a);
        denom += ex;
        float2 q0 = __half22float2(*(const __half2*)&u.x);
        float2 q1 = __half22float2(*(const __half2*)&u.y);
        float2 q2 = __half22float2(*(const __half2*)&u.z);
        float2 q3 = __half22float2(*(const __half2*)&u.w);
        acc[0] = fmaf(q0.x, ex, acc[0]);
        acc[1] = fmaf(q0.y, ex, acc[1]);
        acc[2] = fmaf(q1.x, ex, acc[2]);
        acc[3] = fmaf(q1.y, ex, acc[3]);
        acc[4] = fmaf(q2.x, ex, acc[4]);
        acc[5] = fmaf(q2.y, ex, acc[5]);
        acc[6] = fmaf(q3.x, ex, acc[6]);
        acc[7] = fmaf(q3.y, ex, acc[7]);
    }

    float inv = 1.0f / (denom + 1e-16f);
    float4* o4 = (float4*)out;
    unsigned obase = (unsigned)node * 32 + l * 2;
    o4[obase]     = make_float4(acc[0] * inv, acc[1] * inv, acc[2] * inv, acc[3] * inv);
    o4[obase + 1] = make_float4(acc[4] * inv, acc[5] * inv, acc[6] * inv, acc[7] * inv);

    if (l == 0) g_cnt[node] = 0;                       // self-reset
    if (pair == 0 && lane == 0) g_ready = 0;           // reset prep barrier
}

// ---------------------------------------------------------------------------
extern "C" void kernel_launch(void* const* d_in, const int* in_sizes, int n_in,
                              void* d_out, int out_size) {
    const float* x  = (const float*)d_in[0];
    const int*   ei = (const int*)d_in[1];
    const float* ct = (const float*)d_in[2];
    const float* lw = (const float*)d_in[3];
    const float* lb = (const float*)d_in[4];
    const float* as = (const float*)d_in[5];
    const float* ad = (const float*)d_in[6];
    float* out = (float*)d_out;

    k_fused<<<NBLK_X, 128>>>(x, ei, lw, lb, as, ad, ct);
    {
        long long threads = (long long)(N_NODES / 2) * 32;
        int blocks = (int)((threads + 255) / 256);
        k_node<<<blocks, 256>>>(out);
    }
}

// round 14
// speedup vs baseline: 1.9074x; 1.7842x over previous
#include <cuda_runtime.h>
#include <cuda_fp16.h>

#define N_NODES 50000
#define N_EDGES 600000
#define IN_CH 128
#define HC 128
#define HEADS 4
#define NEG_SLOPE 0.2f
#define CAP 128        // per-node CSR capacity (mean deg 12)
#define NBLK_X 1563    // ceil(50000/32); 1563*384 >= 600000; >= 128 prep blocks
#define PREP_BLOCKS 128

// ---------------- scratch (device globals) -----------------------------------
__device__ __half g_W_h[HC * IN_CH];                 // fp16 weights [o][i]
__device__ float  g_bias[HC];
__device__ float  g_asrc[HC];
__device__ float  g_adst[HC];
__device__ __half g_xt_h[(size_t)N_NODES * HC];      // 12.8 MB fp16 features
__device__ float  g_alpha_src[N_NODES * HEADS];
__device__ float  g_alpha_dst[N_NODES * HEADS];
__device__ int    g_cnt[N_NODES];                    // degree counter; self-reset
__device__ int    g_csr_src[(size_t)N_NODES * CAP];  // 25.6 MB padded CSR
__device__ int    g_ready;                           // prep barrier; self-reset

// ---------------- mma.m16n8k16 f16*f16+f32 wrapper -----------------------------
__device__ __forceinline__ void mma16816(float* d, const unsigned* a, const unsigned* b) {
    asm volatile(
        "mma.sync.aligned.m16n8k16.row.col.f32.f16.f16.f32 "
        "{%0,%1,%2,%3}, {%4,%5,%6,%7}, {%8,%9}, {%0,%1,%2,%3};"
        : "+f"(d[0]), "+f"(d[1]), "+f"(d[2]), "+f"(d[3])
        : "r"(a[0]), "r"(a[1]), "r"(a[2]), "r"(a[3]), "r"(b[0]), "r"(b[1]));
}

// ---------------- kernel 1: fused scatter + prep + tensor-core transform -------
// (a) scatter 3 edges/thread, (b) prep blocks build fp16 W + fp32 bias/att,
// (c) stage x fp16 into smem, (d) device barrier, (e) HMMA GEMM + epilogue.
__global__ void __launch_bounds__(128) k_fused(const float* __restrict__ x,
                                               const int* __restrict__ ei,
                                               const float* __restrict__ lw,
                                               const float* __restrict__ lb,
                                               const float* __restrict__ as,
                                               const float* __restrict__ ad,
                                               const float* __restrict__ ct) {
    int t = threadIdx.x;
    int bid = blockIdx.x;

    // (a) padded-CSR scatter
    {
        int ebase = bid * 384;
        #pragma unroll
        for (int j = 0; j < 3; j++) {
            int e = ebase + j * 128 + t;
            if (e < N_EDGES) {
                int r = __ldg(&ei[e]);
                int c = __ldg(&ei[N_EDGES + e]);
                int pos = atomicAdd(&g_cnt[c], 1);
                if (pos < CAP) g_csr_src[c * CAP + pos] = r;
            }
        }
    }

    // (b) Bezier prep: block b = output column o, thread t = input channel i
    if (bid < PREP_BLOCKS) {
        float c0 = __ldg(&ct[0]), c1 = __ldg(&ct[1]), c2 = __ldg(&ct[2]);
        float w = c0 * __ldg(&lw[bid * IN_CH + t])
                + c1 * __ldg(&lw[IN_CH * HC + bid * IN_CH + t])
                + c2 * __ldg(&lw[2 * IN_CH * HC + bid * IN_CH + t]);
        g_W_h[bid * IN_CH + t] = __float2half_rn(w);
        if (bid == 0) {
            g_bias[t] = c0 * __ldg(&lb[t]) + c1 * __ldg(&lb[HC + t]) + c2 * __ldg(&lb[2 * HC + t]);
            g_asrc[t] = c0 * __ldg(&as[t]) + c1 * __ldg(&as[HC + t]) + c2 * __ldg(&as[2 * HC + t]);
            g_adst[t] = c0 * __ldg(&ad[t]) + c1 * __ldg(&ad[HC + t]) + c2 * __ldg(&ad[2 * HC + t]);
        }
        __syncthreads();
        if (t == 0) {
            __threadfence();
            atomicAdd(&g_ready, 1);
        }
    }

    // (c) stage x fp16 into smem; stride 136 halves (=68 words ≡ 4 mod 32:
    //     conflict-free fragment loads)
    __shared__ __half xs16[32][136];
    int n0 = bid * 32;
    #pragma unroll 4
    for (int p = 0; p < 32; p++) {
        float v = (n0 + p < N_NODES) ? __ldg(&x[(size_t)(n0 + p) * IN_CH + t]) : 0.0f;
        xs16[p][t] = __float2half_rn(v);
    }

    // (d) device barrier: wait for all 128 prep blocks (wave-1 bids)
    if (t == 0) {
        int v;
        do {
            asm volatile("ld.acquire.gpu.global.b32 %0, [%1];" : "=r"(v) : "l"(&g_ready));
            if (v >= PREP_BLOCKS) break;
            __nanosleep(128);
        } while (true);
    }
    __syncthreads();   // also covers xs16

    // (e) HMMA GEMM: warp w computes cols [32w,32w+32) == head w, rows 0..31
    int w = t >> 5;
    int lane = t & 31;
    int g = lane >> 2;
    int tig = lane & 3;
    int cbase = w * 32;

    float d[2][4][4];
    #pragma unroll
    for (int mt = 0; mt < 2; mt++)
        #pragma unroll
        for (int nt = 0; nt < 4; nt++) {
            int c0 = cbase + nt * 8 + 2 * tig;
            float b0 = __ldg(&g_bias[c0]);
            float b1 = __ldg(&g_bias[c0 + 1]);
            d[mt][nt][0] = b0; d[mt][nt][1] = b1;
            d[mt][nt][2] = b0; d[mt][nt][3] = b1;
        }

    #pragma unroll
    for (int ks = 0; ks < 8; ks++) {
        int k0 = ks * 16;
        unsigned afr[2][4], bfr[4][2];
        #pragma unroll
        for (int mt = 0; mt < 2; mt++) {
            int rm = mt * 16;
            afr[mt][0] = *reinterpret_cast<const unsigned*>(&xs16[rm + g][k0 + 2 * tig]);
            afr[mt][1] = *reinterpret_cast<const unsigned*>(&xs16[rm + g + 8][k0 + 2 * tig]);
            afr[mt][2] = *reinterpret_cast<const unsigned*>(&xs16[rm + g][k0 + 2 * tig + 8]);
            afr[mt][3] = *reinterpret_cast<const unsigned*>(&xs16[rm + g + 8][k0 + 2 * tig + 8]);
        }
        #pragma unroll
        for (int nt = 0; nt < 4; nt++) {
            int row = cbase + nt * 8 + g;   // W row = output col
            bfr[nt][0] = *reinterpret_cast<const unsigned*>(&g_W_h[row * IN_CH + k0 + 2 * tig]);
            bfr[nt][1] = *reinterpret_cast<const unsigned*>(&g_W_h[row * IN_CH + k0 + 2 * tig + 8]);
        }
        #pragma unroll
        for (int mt = 0; mt < 2; mt++)
            #pragma unroll
            for (int nt = 0; nt < 4; nt++)
                mma16816(d[mt][nt], afr[mt], bfr[nt]);
    }

    // epilogue: store xt fp16 + per-head attention dot products from fragments
    #pragma unroll
    for (int mt = 0; mt < 2; mt++) {
        int r0 = n0 + mt * 16 + g;
        int r1 = r0 + 8;
        float vs0 = 0.f, vs1 = 0.f, vd0 = 0.f, vd1 = 0.f;
        #pragma unroll
        for (int nt = 0; nt < 4; nt++) {
            int c0 = cbase + nt * 8 + 2 * tig;
            float A0 = __ldg(&g_asrc[c0]), A1 = __ldg(&g_asrc[c0 + 1]);
            float D0 = __ldg(&g_adst[c0]), D1 = __ldg(&g_adst[c0 + 1]);
            vs0 += d[mt][nt][0] * A0 + d[mt][nt][1] * A1;
            vs1 += d[mt][nt][2] * A0 + d[mt][nt][3] * A1;
            vd0 += d[mt][nt][0] * D0 + d[mt][nt][1] * D1;
            vd1 += d[mt][nt][2] * D0 + d[mt][nt][3] * D1;
            if (r0 < N_NODES)
                *reinterpret_cast<__half2*>(&g_xt_h[(size_t)r0 * HC + c0]) =
                    __floats2half2_rn(d[mt][nt][0], d[mt][nt][1]);
            if (r1 < N_NODES)
                *reinterpret_cast<__half2*>(&g_xt_h[(size_t)r1 * HC + c0]) =
                    __floats2half2_rn(d[mt][nt][2], d[mt][nt][3]);
        }
        // reduce over the 4 lanes of the quad (tig)
        vs0 += __shfl_xor_sync(0xffffffffu, vs0, 1); vs0 += __shfl_xor_sync(0xffffffffu, vs0, 2);
        vs1 += __shfl_xor_sync(0xffffffffu, vs1, 1); vs1 += __shfl_xor_sync(0xffffffffu, vs1, 2);
        vd0 += __shfl_xor_sync(0xffffffffu, vd0, 1); vd0 += __shfl_xor_sync(0xffffffffu, vd0, 2);
        vd1 += __shfl_xor_sync(0xffffffffu, vd1, 1); vd1 += __shfl_xor_sync(0xffffffffu, vd1, 2);
        if (tig == 0) {
            if (r0 < N_NODES) {
                g_alpha_src[r0 * HEADS + w] = vs0;
                g_alpha_dst[r0 * HEADS + w] = vd0;
            }
            if (r1 < N_NODES) {
                g_alpha_src[r1 * HEADS + w] = vs1;
                g_alpha_dst[r1 * HEADS + w] = vd1;
            }
        }
    }
}

// ---------------- kernel 2: fused softmax (no-max) + aggregation ---------------
// R10 best variant: 2 nodes/warp, chunk-4 gathers (8 in flight per warp).
__global__ void __launch_bounds__(256) k_node(float* __restrict__ out) {
    int pair = (int)(((long long)blockIdx.x * blockDim.x + threadIdx.x) >> 5);
    if (pair >= N_NODES / 2) return;
    int lane = threadIdx.x & 31;
    int node = pair * 2 + (lane >> 4);
    int l = lane & 15;
    int h = l >> 2;

    int deg = g_cnt[node];
    if (deg > CAP) deg = CAP;
    unsigned base = (unsigned)node * CAP;
    float ad = __ldg(&g_alpha_dst[node * HEADS + h]);

    float denom = 0.0f;
    float acc[8];
    #pragma unroll
    for (int k = 0; k < 8; k++) acc[k] = 0.0f;

    const uint4* xt4 = (const uint4*)g_xt_h;

    int e = 0;
    for (; e + 4 <= deg; e += 4) {
        int s[4]; float a[4]; uint4 u[4];
        #pragma unroll
        for (int j = 0; j < 4; j++) s[j] = __ldg(&g_csr_src[base + e + j]);
        #pragma unroll
        for (int j = 0; j < 4; j++) a[j] = __ldg(&g_alpha_src[s[j] * HEADS + h]) + ad;
        #pragma unroll
        for (int j = 0; j < 4; j++) u[j] = __ldg(&xt4[(unsigned)s[j] * 16 + l]);
        #pragma unroll
        for (int j = 0; j < 4; j++) {
            float aj = a[j];
            aj = (aj > 0.f) ? aj : NEG_SLOPE * aj;
            float ex = __expf(aj);
            denom += ex;
            float2 p0 = __half22float2(*(const __half2*)&u[j].x);
            float2 p1 = __half22float2(*(const __half2*)&u[j].y);
            float2 p2 = __half22float2(*(const __half2*)&u[j].z);
            float2 p3 = __half22float2(*(const __half2*)&u[j].w);
            acc[0] = fmaf(p0.x, ex, acc[0]);
            acc[1] = fmaf(p0.y, ex, acc[1]);
            acc[2] = fmaf(p1.x, ex, acc[2]);
            acc[3] = fmaf(p1.y, ex, acc[3]);
            acc[4] = fmaf(p2.x, ex, acc[4]);
            acc[5] = fmaf(p2.y, ex, acc[5]);
            acc[6] = fmaf(p3.x, ex, acc[6]);
            acc[7] = fmaf(p3.y, ex, acc[7]);
        }
    }
    for (; e < deg; e++) {
        int s = __ldg(&g_csr_src[base + e]);
        float a = __ldg(&g_alpha_src[s * HEADS + h]) + ad;
        a = (a > 0.f) ? a : NEG_SLOPE * a;
        uint4 u = __ldg(&xt4[(unsigned)s * 16 + l]);
        float ex = __expf(a);
        denom += ex;
        float2 p0 = __half22float2(*(const __half2*)&u.x);
        float2 p1 = __half22float2(*(const __half2*)&u.y);
        float2 p2 = __half22float2(*(const __half2*)&u.z);
        float2 p3 = __half22float2(*(const __half2*)&u.w);
        acc[0] = fmaf(p0.x, ex, acc[0]);
        acc[1] = fmaf(p0.y, ex, acc[1]);
        acc[2] = fmaf(p1.x, ex, acc[2]);
        acc[3] = fmaf(p1.y, ex, acc[3]);
        acc[4] = fmaf(p2.x, ex, acc[4]);
        acc[5] = fmaf(p2.y, ex, acc[5]);
        acc[6] = fmaf(p3.x, ex, acc[6]);
        acc[7] = fmaf(p3.y, ex, acc[7]);
    }

    float inv = 1.0f / (denom + 1e-16f);
    float4* o4 = (float4*)out;
    unsigned obase = (unsigned)node * 32 + l * 2;
    o4[obase]     = make_float4(acc[0] * inv, acc[1] * inv, acc[2] * inv, acc[3] * inv);
    o4[obase + 1] = make_float4(acc[4] * inv, acc[5] * inv, acc[6] * inv, acc[7] * inv);

    if (l == 0) g_cnt[node] = 0;                       // self-reset
    if (pair == 0 && lane == 0) g_ready = 0;           // reset prep barrier
}

// ---------------------------------------------------------------------------
extern "C" void kernel_launch(void* const* d_in, const int* in_sizes, int n_in,
                              void* d_out, int out_size) {
    const float* x  = (const float*)d_in[0];
    const int*   ei = (const int*)d_in[1];
    const float* ct = (const float*)d_in[2];
    const float* lw = (const float*)d_in[3];
    const float* lb = (const float*)d_in[4];
    const float* as = (const float*)d_in[5];
    const float* ad = (const float*)d_in[6];
    float* out = (float*)d_out;

    k_fused<<<NBLK_X, 128>>>(x, ei, lw, lb, as, ad, ct);
    {
        long long threads = (long long)(N_NODES / 2) * 32;
        int blocks = (int)((threads + 255) / 256);
        k_node<<<blocks, 256>>>(out);
    }
}